// round 7
// baseline (speedup 1.0000x reference)
#include <cuda_runtime.h>
#include <math.h>

// Problem shape (fixed by the dataset)
#define B_DIM 256
#define K_DIM 512
#define D_DIM 1024
#define KPB   32                      // k rows per tile (8 warps x 4 rows)
#define KYN   (K_DIM / KPB)           // 16 tiles per batch row
#define NTILE (B_DIM * KYN)           // 4096 tiles
#define GRID  592                     // 148 SMs x 4 resident blocks
#define CHUNK_BIG 7                   // 544 blocks x 7 + 48 blocks x 6 = 4096
#define NBIG  544
#define INV_T 14.2857142857142857f    // 1/0.07

// Scratch (no allocations). Fully overwritten each launch; ticket returns
// to 0 at the end of every launch (graph-replay safe).
__device__ double2      g_part[GRID];
__device__ unsigned int g_ticket;      // zero-initialized at module load

// smem ballast: pins exactly 4 blocks/SM so all GRID blocks are co-resident
// and the static chunk assignment is balanced.
#define QS_PAD 2880                   // 2880 * 16B = 46080 B

__global__ __launch_bounds__(256, 4)
void fused_kernel(const float* __restrict__ bg_img,
                  const float* __restrict__ fg_pro,
                  const float* __restrict__ bg_pro,
                  float* __restrict__ out) {
    const int tid  = threadIdx.x;
    const int warp = tid >> 5;
    const int lane = tid & 31;

    __shared__ float4 q_s[QS_PAD];           // first 256 entries = RAW query row
    __shared__ float  w_red[16];             // 8 ss + 8 fd warp partials
    __shared__ double sacc[8];
    __shared__ bool   s_is_last;

    // contiguous chunk for this block
    const int bid = blockIdx.x;
    const int lo  = (bid < NBIG) ? bid * CHUNK_BIG
                                 : NBIG * CHUNK_BIG + (bid - NBIG) * (CHUNK_BIG - 1);
    const int hi  = lo + ((bid < NBIG) ? CHUNK_BIG : CHUNK_BIG - 1);

    double acc_lane = 0.0;   // per-lane running sum of exp(bg_logit/T)
    double fg_acc   = 0.0;   // meaningful on tid 0 only
    float  scale    = 0.f;   // inv_norm(b) * INV_T, cached per b
    int    cur_b    = -1;

    for (int t = lo; t < hi; t++) {
        const int b  = t >> 4;          // t / KYN
        const int ky = t & (KYN - 1);   // t % KYN

        if (b != cur_b) {
            // ---- per-b setup: publish RAW q row, reduce sumsq (+fg dot) ----
            __syncthreads();   // previous tile's readers of q_s/w_red are done

            const float4* qrow = reinterpret_cast<const float4*>(bg_img + (size_t)b * D_DIM);
            float4 qv = qrow[tid];
            float ss = qv.x*qv.x + qv.y*qv.y + qv.z*qv.z + qv.w*qv.w;

            float fd = 0.f;
            if (ky == 0) {   // this block owns b's fg tile
                const float4* frow = reinterpret_cast<const float4*>(fg_pro + (size_t)b * D_DIM);
                float4 f = frow[tid];
                fd = qv.x*f.x + qv.y*f.y + qv.z*f.z + qv.w*f.w;
            }
            #pragma unroll
            for (int o = 16; o; o >>= 1) {
                ss += __shfl_xor_sync(0xFFFFFFFFu, ss, o);
                fd += __shfl_xor_sync(0xFFFFFFFFu, fd, o);
            }
            if (lane == 0) { w_red[warp] = ss; w_red[8 + warp] = fd; }
            q_s[tid] = qv;                       // raw (unnormalized)
            __syncthreads();                     // q_s + w_red visible

            float tss = 0.f;
            #pragma unroll
            for (int i = 0; i < 8; i++) tss += w_red[i];
            const float inv = 1.0f / sqrtf(tss);
            scale = inv * INV_T;

            if (tid == 0 && ky == 0) {
                float tfd = 0.f;
                #pragma unroll
                for (int i = 0; i < 8; i++) tfd += w_red[8 + i];
                fg_acc += (double)expf(tfd * inv * INV_T);
            }
            cur_b = b;
        }
        // (b unchanged: no sync — next tile's loads overlap previous tail)

        // ---- hot loop: warp owns 4 k rows; pure LDG/LDS/FFMA ----
        const int k0 = ky * KPB + warp * 4;
        const float* pbase = bg_pro + ((size_t)b * K_DIM + k0) * D_DIM;
        const float4* p0 = reinterpret_cast<const float4*>(pbase + (size_t)0 * D_DIM);
        const float4* p1 = reinterpret_cast<const float4*>(pbase + (size_t)1 * D_DIM);
        const float4* p2 = reinterpret_cast<const float4*>(pbase + (size_t)2 * D_DIM);
        const float4* p3 = reinterpret_cast<const float4*>(pbase + (size_t)3 * D_DIM);

        float s0 = 0.f, s1 = 0.f, s2 = 0.f, s3 = 0.f;
        #pragma unroll
        for (int i = 0; i < 8; i++) {
            const int idx = i * 32 + lane;
            float4 qi = q_s[idx];
            float4 a0 = __ldcs(&p0[idx]);
            float4 a1 = __ldcs(&p1[idx]);
            float4 a2 = __ldcs(&p2[idx]);
            float4 a3 = __ldcs(&p3[idx]);
            s0 = fmaf(qi.x, a0.x, s0); s0 = fmaf(qi.y, a0.y, s0);
            s0 = fmaf(qi.z, a0.z, s0); s0 = fmaf(qi.w, a0.w, s0);
            s1 = fmaf(qi.x, a1.x, s1); s1 = fmaf(qi.y, a1.y, s1);
            s1 = fmaf(qi.z, a1.z, s1); s1 = fmaf(qi.w, a1.w, s1);
            s2 = fmaf(qi.x, a2.x, s2); s2 = fmaf(qi.y, a2.y, s2);
            s2 = fmaf(qi.z, a2.z, s2); s2 = fmaf(qi.w, a2.w, s2);
            s3 = fmaf(qi.x, a3.x, s3); s3 = fmaf(qi.y, a3.y, s3);
            s3 = fmaf(qi.z, a3.z, s3); s3 = fmaf(qi.w, a3.w, s3);
        }

        // ---- tail: 4 shfl trees; inv applied at the exponent ----
        float r;
        r = s0;
        #pragma unroll
        for (int o = 16; o; o >>= 1) r += __shfl_xor_sync(0xFFFFFFFFu, r, o);
        if (lane == 0) acc_lane += (double)expf(r * scale);
        r = s1;
        #pragma unroll
        for (int o = 16; o; o >>= 1) r += __shfl_xor_sync(0xFFFFFFFFu, r, o);
        if (lane == 1) acc_lane += (double)expf(r * scale);
        r = s2;
        #pragma unroll
        for (int o = 16; o; o >>= 1) r += __shfl_xor_sync(0xFFFFFFFFu, r, o);
        if (lane == 2) acc_lane += (double)expf(r * scale);
        r = s3;
        #pragma unroll
        for (int o = 16; o; o >>= 1) r += __shfl_xor_sync(0xFFFFFFFFu, r, o);
        if (lane == 3) acc_lane += (double)expf(r * scale);
    }

    // ---- once-per-block reduction + ticketed finish ----
    #pragma unroll
    for (int o = 16; o; o >>= 1)
        acc_lane += __shfl_xor_sync(0xFFFFFFFFu, acc_lane, o);
    __syncthreads();   // done with q_s/w_red from last tile
    if (lane == 0) sacc[warp] = acc_lane;
    __syncthreads();

    if (tid == 0) {
        double tsum = 0.0;
        #pragma unroll
        for (int i = 0; i < 8; i++) tsum += sacc[i];
        g_part[bid] = make_double2(tsum, fg_acc);
        __threadfence();
        unsigned int done = atomicAdd(&g_ticket, 1u);
        s_is_last = (done == (unsigned int)(GRID - 1));
    }
    __syncthreads();

    if (s_is_last) {
        const volatile double* vp = reinterpret_cast<const volatile double*>(g_part);
        double pos = 0.0, fg = 0.0;
        for (int i = tid; i < GRID; i += 256) {
            pos += vp[2 * i + 0];
            fg  += vp[2 * i + 1];
        }
        #pragma unroll
        for (int o = 16; o; o >>= 1) {
            pos += __shfl_xor_sync(0xFFFFFFFFu, pos, o);
            fg  += __shfl_xor_sync(0xFFFFFFFFu, fg,  o);
        }
        __shared__ double w_pos[8], w_fg[8];
        if (lane == 0) { w_pos[warp] = pos; w_fg[warp] = fg; }
        __syncthreads();
        if (tid == 0) {
            double P = 0.0, F = 0.0;
            #pragma unroll
            for (int i = 0; i < 8; i++) { P += w_pos[i]; F += w_fg[i]; }
            // -log(pos/neg) = log1p(K * F / S)
            out[0] = (float)log1p(F * (double)K_DIM / P);
            g_ticket = 0;   // restore for next graph replay
        }
    }
}

extern "C" void kernel_launch(void* const* d_in, const int* in_sizes, int n_in,
                              void* d_out, int out_size) {
    const float* bg_img = (const float*)d_in[0];   // [B, D]
    const float* fg_pro = (const float*)d_in[1];   // [B, D]
    const float* bg_pro = (const float*)d_in[2];   // [B, K, D]
    float* out = (float*)d_out;

    fused_kernel<<<GRID, 256>>>(bg_img, fg_pro, bg_pro, out);
}

// round 8
// speedup vs baseline: 1.0055x; 1.0055x over previous
#include <cuda_runtime.h>
#include <math.h>

// Problem shape (fixed by the dataset)
#define B_DIM 256
#define K_DIM 512
#define D_DIM 1024
#define KPB   32                      // k rows per tile (8 warps x 4 rows)
#define KYN   (K_DIM / KPB)           // 16 tiles per batch row
#define NTILE (B_DIM * KYN)           // 4096 tiles
#define GRID  592                     // 148 SMs x 4 resident blocks
#define INV_T 14.2857142857142857f    // 1/0.07

// Scratch (no allocations). Fully overwritten each launch; both counters
// return to 0 at the end of every launch (graph-replay safe).
__device__ double2      g_part[GRID];
__device__ unsigned int g_ticket;      // completion ticket (zero-init)
__device__ unsigned int g_work;        // work-stealing tile counter (zero-init)

// smem ballast: pins exactly 4 blocks/SM so all GRID blocks are co-resident.
#define QS_PAD 2880                   // 2880 * 16B = 46080 B

__global__ __launch_bounds__(256, 4)
void fused_kernel(const float* __restrict__ bg_img,
                  const float* __restrict__ fg_pro,
                  const float* __restrict__ bg_pro,
                  float* __restrict__ out) {
    const int tid  = threadIdx.x;
    const int warp = tid >> 5;
    const int lane = tid & 31;

    __shared__ float4 q_s[QS_PAD];           // first 256 entries = RAW query row
    __shared__ float  w_red[16];             // 8 ss + 8 fd warp partials
    __shared__ double sacc[8];
    __shared__ int    s_t;                   // current tile (broadcast)
    __shared__ bool   s_is_last;

    double acc_lane = 0.0;   // per-lane running sum of exp(bg_logit/T)
    double fg_acc   = 0.0;   // meaningful on tid 0 only
    float  scale    = 0.f;   // inv_norm(b) * INV_T, cached per b
    int    cur_b    = -1;

    for (;;) {
        // ---- steal next tile ----
        if (tid == 0) s_t = (int)atomicAdd(&g_work, 1u);
        __syncthreads();               // broadcast s_t; also fences q_s reuse
        const int t = s_t;
        if (t >= NTILE) break;

        const int b  = t >> 4;          // t / KYN
        const int ky = t & (KYN - 1);   // t % KYN

        if (b != cur_b) {
            // ---- per-b setup: publish RAW q row, reduce sumsq (+fg dot) ----
            const float4* qrow = reinterpret_cast<const float4*>(bg_img + (size_t)b * D_DIM);
            float4 qv = qrow[tid];
            float ss = qv.x*qv.x + qv.y*qv.y + qv.z*qv.z + qv.w*qv.w;

            float fd = 0.f;
            if (ky == 0) {   // this block owns b's fg tile
                const float4* frow = reinterpret_cast<const float4*>(fg_pro + (size_t)b * D_DIM);
                float4 f = frow[tid];
                fd = qv.x*f.x + qv.y*f.y + qv.z*f.z + qv.w*f.w;
            }
            #pragma unroll
            for (int o = 16; o; o >>= 1) {
                ss += __shfl_xor_sync(0xFFFFFFFFu, ss, o);
                fd += __shfl_xor_sync(0xFFFFFFFFu, fd, o);
            }
            if (lane == 0) { w_red[warp] = ss; w_red[8 + warp] = fd; }
            q_s[tid] = qv;                       // raw (unnormalized)
            __syncthreads();                     // q_s + w_red visible

            float tss = 0.f;
            #pragma unroll
            for (int i = 0; i < 8; i++) tss += w_red[i];
            const float inv = 1.0f / sqrtf(tss);
            scale = inv * INV_T;

            if (tid == 0 && ky == 0) {
                float tfd = 0.f;
                #pragma unroll
                for (int i = 0; i < 8; i++) tfd += w_red[8 + i];
                fg_acc += (double)expf(tfd * inv * INV_T);
            }
            cur_b = b;
        } else if (ky == 0) {
            // rare: fg tile stolen after q already cached — recompute fd
            const float4* qrow = reinterpret_cast<const float4*>(bg_img + (size_t)b * D_DIM);
            const float4* frow = reinterpret_cast<const float4*>(fg_pro + (size_t)b * D_DIM);
            float4 qv = qrow[tid];
            float4 f  = frow[tid];
            float fd = qv.x*f.x + qv.y*f.y + qv.z*f.z + qv.w*f.w;
            #pragma unroll
            for (int o = 16; o; o >>= 1) fd += __shfl_xor_sync(0xFFFFFFFFu, fd, o);
            if (lane == 0) w_red[8 + warp] = fd;
            __syncthreads();
            if (tid == 0) {
                float tfd = 0.f;
                #pragma unroll
                for (int i = 0; i < 8; i++) tfd += w_red[8 + i];
                fg_acc += (double)expf(tfd * scale);
            }
        }

        // ---- hot loop: warp owns 4 k rows; pure LDG/LDS/FFMA ----
        const int k0 = ky * KPB + warp * 4;
        const float* pbase = bg_pro + ((size_t)b * K_DIM + k0) * D_DIM;
        const float4* p0 = reinterpret_cast<const float4*>(pbase + (size_t)0 * D_DIM);
        const float4* p1 = reinterpret_cast<const float4*>(pbase + (size_t)1 * D_DIM);
        const float4* p2 = reinterpret_cast<const float4*>(pbase + (size_t)2 * D_DIM);
        const float4* p3 = reinterpret_cast<const float4*>(pbase + (size_t)3 * D_DIM);

        float s0 = 0.f, s1 = 0.f, s2 = 0.f, s3 = 0.f;
        #pragma unroll
        for (int i = 0; i < 8; i++) {
            const int idx = i * 32 + lane;
            float4 qi = q_s[idx];
            float4 a0 = __ldcs(&p0[idx]);
            float4 a1 = __ldcs(&p1[idx]);
            float4 a2 = __ldcs(&p2[idx]);
            float4 a3 = __ldcs(&p3[idx]);
            s0 = fmaf(qi.x, a0.x, s0); s0 = fmaf(qi.y, a0.y, s0);
            s0 = fmaf(qi.z, a0.z, s0); s0 = fmaf(qi.w, a0.w, s0);
            s1 = fmaf(qi.x, a1.x, s1); s1 = fmaf(qi.y, a1.y, s1);
            s1 = fmaf(qi.z, a1.z, s1); s1 = fmaf(qi.w, a1.w, s1);
            s2 = fmaf(qi.x, a2.x, s2); s2 = fmaf(qi.y, a2.y, s2);
            s2 = fmaf(qi.z, a2.z, s2); s2 = fmaf(qi.w, a2.w, s2);
            s3 = fmaf(qi.x, a3.x, s3); s3 = fmaf(qi.y, a3.y, s3);
            s3 = fmaf(qi.z, a3.z, s3); s3 = fmaf(qi.w, a3.w, s3);
        }

        // ---- tail: 4 shfl trees; inv applied at the exponent ----
        float r;
        r = s0;
        #pragma unroll
        for (int o = 16; o; o >>= 1) r += __shfl_xor_sync(0xFFFFFFFFu, r, o);
        if (lane == 0) acc_lane += (double)expf(r * scale);
        r = s1;
        #pragma unroll
        for (int o = 16; o; o >>= 1) r += __shfl_xor_sync(0xFFFFFFFFu, r, o);
        if (lane == 1) acc_lane += (double)expf(r * scale);
        r = s2;
        #pragma unroll
        for (int o = 16; o; o >>= 1) r += __shfl_xor_sync(0xFFFFFFFFu, r, o);
        if (lane == 2) acc_lane += (double)expf(r * scale);
        r = s3;
        #pragma unroll
        for (int o = 16; o; o >>= 1) r += __shfl_xor_sync(0xFFFFFFFFu, r, o);
        if (lane == 3) acc_lane += (double)expf(r * scale);
    }

    // ---- once-per-block reduction + ticketed finish ----
    #pragma unroll
    for (int o = 16; o; o >>= 1)
        acc_lane += __shfl_xor_sync(0xFFFFFFFFu, acc_lane, o);
    if (lane == 0) sacc[warp] = acc_lane;
    __syncthreads();

    if (tid == 0) {
        double tsum = 0.0;
        #pragma unroll
        for (int i = 0; i < 8; i++) tsum += sacc[i];
        g_part[blockIdx.x] = make_double2(tsum, fg_acc);
        __threadfence();
        unsigned int done = atomicAdd(&g_ticket, 1u);
        s_is_last = (done == (unsigned int)(GRID - 1));
    }
    __syncthreads();

    if (s_is_last) {
        const volatile double* vp = reinterpret_cast<const volatile double*>(g_part);
        double pos = 0.0, fg = 0.0;
        for (int i = tid; i < GRID; i += 256) {
            pos += vp[2 * i + 0];
            fg  += vp[2 * i + 1];
        }
        #pragma unroll
        for (int o = 16; o; o >>= 1) {
            pos += __shfl_xor_sync(0xFFFFFFFFu, pos, o);
            fg  += __shfl_xor_sync(0xFFFFFFFFu, fg,  o);
        }
        __shared__ double w_pos[8], w_fg[8];
        if (lane == 0) { w_pos[warp] = pos; w_fg[warp] = fg; }
        __syncthreads();
        if (tid == 0) {
            double P = 0.0, F = 0.0;
            #pragma unroll
            for (int i = 0; i < 8; i++) { P += w_pos[i]; F += w_fg[i]; }
            // -log(pos/neg) = log1p(K * F / S)
            out[0] = (float)log1p(F * (double)K_DIM / P);
            g_work   = 0;   // restore for next graph replay
            g_ticket = 0;
        }
    }
}

extern "C" void kernel_launch(void* const* d_in, const int* in_sizes, int n_in,
                              void* d_out, int out_size) {
    const float* bg_img = (const float*)d_in[0];   // [B, D]
    const float* fg_pro = (const float*)d_in[1];   // [B, D]
    const float* bg_pro = (const float*)d_in[2];   // [B, K, D]
    float* out = (float*)d_out;

    fused_kernel<<<GRID, 256>>>(bg_img, fg_pro, bg_pro, out);
}

// round 9
// speedup vs baseline: 1.0155x; 1.0100x over previous
#include <cuda_runtime.h>
#include <math.h>

// Problem shape (fixed by the dataset)
#define B_DIM 256
#define K_DIM 512
#define D_DIM 1024
#define KPB   32                      // k rows per tile (8 warps x 4 rows)
#define KYN   (K_DIM / KPB)           // 16 tiles per batch row
#define NTILE (B_DIM * KYN)           // 4096 tiles
#define GRID  592                     // 148 SMs x 4 resident blocks
#define INV_T 14.2857142857142857f    // 1/0.07

// Scratch (no allocations). Fully overwritten each launch; both counters
// return to 0 at the end of every launch (graph-replay safe).
__device__ double2      g_part[GRID];
__device__ unsigned int g_ticket;      // completion ticket (zero-init)
__device__ unsigned int g_work;        // work-stealing tile counter (zero-init)

// smem ballast: pins exactly 4 blocks/SM so all GRID blocks are co-resident.
#define QS_PAD 2880                   // 2880 * 16B = 46080 B

__global__ __launch_bounds__(256, 4)
void fused_kernel(const float* __restrict__ bg_img,
                  const float* __restrict__ fg_pro,
                  const float* __restrict__ bg_pro,
                  float* __restrict__ out) {
    const int tid  = threadIdx.x;
    const int warp = tid >> 5;
    const int lane = tid & 31;

    __shared__ float4 q_s[QS_PAD];           // first 256 entries = RAW query row
    __shared__ float  w_red[16];             // 8 ss + 8 fd warp partials
    __shared__ double sacc[8];
    __shared__ int    s_t;                   // current tile (broadcast)
    __shared__ bool   s_is_last;

    double acc_lane = 0.0;   // per-lane running sum of exp(bg_logit/T)
    double fg_acc   = 0.0;   // meaningful on tid 0 only
    float  scale    = 0.f;   // inv_norm(b) * INV_T, cached per b
    int    cur_b    = -1;
    int    next_t   = 0;     // tid 0's prefetched tile index

    // prefetch first tile
    if (tid == 0) next_t = (int)atomicAdd(&g_work, 1u);

    for (;;) {
        // publish current tile, immediately prefetch the next one (latency
        // of this ATOMG is hidden under the ~12us of tile streaming below)
        if (tid == 0) {
            s_t = next_t;
            next_t = (int)atomicAdd(&g_work, 1u);
        }
        __syncthreads();               // broadcast s_t; also fences q_s reuse
        const int t = s_t;
        if (t >= NTILE) break;

        const int b  = t >> 4;          // t / KYN
        const int ky = t & (KYN - 1);   // t % KYN

        if (b != cur_b) {
            // ---- per-b setup: publish RAW q row, reduce sumsq (+fg dot) ----
            const float4* qrow = reinterpret_cast<const float4*>(bg_img + (size_t)b * D_DIM);
            float4 qv = qrow[tid];
            float ss = qv.x*qv.x + qv.y*qv.y + qv.z*qv.z + qv.w*qv.w;

            float fd = 0.f;
            if (ky == 0) {   // this block owns b's fg tile
                const float4* frow = reinterpret_cast<const float4*>(fg_pro + (size_t)b * D_DIM);
                float4 f = frow[tid];
                fd = qv.x*f.x + qv.y*f.y + qv.z*f.z + qv.w*f.w;
            }
            #pragma unroll
            for (int o = 16; o; o >>= 1) {
                ss += __shfl_xor_sync(0xFFFFFFFFu, ss, o);
                fd += __shfl_xor_sync(0xFFFFFFFFu, fd, o);
            }
            if (lane == 0) { w_red[warp] = ss; w_red[8 + warp] = fd; }
            q_s[tid] = qv;                       // raw (unnormalized)
            __syncthreads();                     // q_s + w_red visible

            float tss = 0.f;
            #pragma unroll
            for (int i = 0; i < 8; i++) tss += w_red[i];
            const float inv = 1.0f / sqrtf(tss);
            scale = inv * INV_T;

            if (tid == 0 && ky == 0) {
                float tfd = 0.f;
                #pragma unroll
                for (int i = 0; i < 8; i++) tfd += w_red[8 + i];
                fg_acc += (double)expf(tfd * inv * INV_T);
            }
            cur_b = b;
        } else if (ky == 0) {
            // fg tile stolen while q already cached — compute fd only
            const float4* qrow = reinterpret_cast<const float4*>(bg_img + (size_t)b * D_DIM);
            const float4* frow = reinterpret_cast<const float4*>(fg_pro + (size_t)b * D_DIM);
            float4 qv = qrow[tid];
            float4 f  = frow[tid];
            float fd = qv.x*f.x + qv.y*f.y + qv.z*f.z + qv.w*f.w;
            #pragma unroll
            for (int o = 16; o; o >>= 1) fd += __shfl_xor_sync(0xFFFFFFFFu, fd, o);
            if (lane == 0) w_red[8 + warp] = fd;
            __syncthreads();
            if (tid == 0) {
                float tfd = 0.f;
                #pragma unroll
                for (int i = 0; i < 8; i++) tfd += w_red[8 + i];
                fg_acc += (double)expf(tfd * scale);
            }
        }

        // ---- hot loop: warp owns 4 k rows; pure LDG/LDS/FFMA ----
        const int k0 = ky * KPB + warp * 4;
        const float* pbase = bg_pro + ((size_t)b * K_DIM + k0) * D_DIM;
        const float4* p0 = reinterpret_cast<const float4*>(pbase + (size_t)0 * D_DIM);
        const float4* p1 = reinterpret_cast<const float4*>(pbase + (size_t)1 * D_DIM);
        const float4* p2 = reinterpret_cast<const float4*>(pbase + (size_t)2 * D_DIM);
        const float4* p3 = reinterpret_cast<const float4*>(pbase + (size_t)3 * D_DIM);

        float s0 = 0.f, s1 = 0.f, s2 = 0.f, s3 = 0.f;
        #pragma unroll
        for (int i = 0; i < 8; i++) {
            const int idx = i * 32 + lane;
            float4 qi = q_s[idx];
            float4 a0 = __ldcs(&p0[idx]);
            float4 a1 = __ldcs(&p1[idx]);
            float4 a2 = __ldcs(&p2[idx]);
            float4 a3 = __ldcs(&p3[idx]);
            s0 = fmaf(qi.x, a0.x, s0); s0 = fmaf(qi.y, a0.y, s0);
            s0 = fmaf(qi.z, a0.z, s0); s0 = fmaf(qi.w, a0.w, s0);
            s1 = fmaf(qi.x, a1.x, s1); s1 = fmaf(qi.y, a1.y, s1);
            s1 = fmaf(qi.z, a1.z, s1); s1 = fmaf(qi.w, a1.w, s1);
            s2 = fmaf(qi.x, a2.x, s2); s2 = fmaf(qi.y, a2.y, s2);
            s2 = fmaf(qi.z, a2.z, s2); s2 = fmaf(qi.w, a2.w, s2);
            s3 = fmaf(qi.x, a3.x, s3); s3 = fmaf(qi.y, a3.y, s3);
            s3 = fmaf(qi.z, a3.z, s3); s3 = fmaf(qi.w, a3.w, s3);
        }

        // ---- tail: 4 shfl trees; inv applied at the exponent ----
        float r;
        r = s0;
        #pragma unroll
        for (int o = 16; o; o >>= 1) r += __shfl_xor_sync(0xFFFFFFFFu, r, o);
        if (lane == 0) acc_lane += (double)expf(r * scale);
        r = s1;
        #pragma unroll
        for (int o = 16; o; o >>= 1) r += __shfl_xor_sync(0xFFFFFFFFu, r, o);
        if (lane == 1) acc_lane += (double)expf(r * scale);
        r = s2;
        #pragma unroll
        for (int o = 16; o; o >>= 1) r += __shfl_xor_sync(0xFFFFFFFFu, r, o);
        if (lane == 2) acc_lane += (double)expf(r * scale);
        r = s3;
        #pragma unroll
        for (int o = 16; o; o >>= 1) r += __shfl_xor_sync(0xFFFFFFFFu, r, o);
        if (lane == 3) acc_lane += (double)expf(r * scale);
    }

    // ---- once-per-block reduction + ticketed finish ----
    #pragma unroll
    for (int o = 16; o; o >>= 1)
        acc_lane += __shfl_xor_sync(0xFFFFFFFFu, acc_lane, o);
    if (lane == 0) sacc[warp] = acc_lane;
    __syncthreads();

    if (tid == 0) {
        double tsum = 0.0;
        #pragma unroll
        for (int i = 0; i < 8; i++) tsum += sacc[i];
        g_part[blockIdx.x] = make_double2(tsum, fg_acc);
        __threadfence();
        unsigned int done = atomicAdd(&g_ticket, 1u);
        s_is_last = (done == (unsigned int)(GRID - 1));
    }
    __syncthreads();

    if (s_is_last) {
        const volatile double* vp = reinterpret_cast<const volatile double*>(g_part);
        double pos = 0.0, fg = 0.0;
        for (int i = tid; i < GRID; i += 256) {
            pos += vp[2 * i + 0];
            fg  += vp[2 * i + 1];
        }
        #pragma unroll
        for (int o = 16; o; o >>= 1) {
            pos += __shfl_xor_sync(0xFFFFFFFFu, pos, o);
            fg  += __shfl_xor_sync(0xFFFFFFFFu, fg,  o);
        }
        __shared__ double w_pos[8], w_fg[8];
        if (lane == 0) { w_pos[warp] = pos; w_fg[warp] = fg; }
        __syncthreads();
        if (tid == 0) {
            double P = 0.0, F = 0.0;
            #pragma unroll
            for (int i = 0; i < 8; i++) { P += w_pos[i]; F += w_fg[i]; }
            // -log(pos/neg) = log1p(K * F / S)
            out[0] = (float)log1p(F * (double)K_DIM / P);
            g_work   = 0;   // restore for next graph replay
            g_ticket = 0;
        }
    }
}

extern "C" void kernel_launch(void* const* d_in, const int* in_sizes, int n_in,
                              void* d_out, int out_size) {
    const float* bg_img = (const float*)d_in[0];   // [B, D]
    const float* fg_pro = (const float*)d_in[1];   // [B, D]
    const float* bg_pro = (const float*)d_in[2];   // [B, K, D]
    float* out = (float*)d_out;

    fused_kernel<<<GRID, 256>>>(bg_img, fg_pro, bg_pro, out);
}